// round 3
// baseline (speedup 1.0000x reference)
#include <cuda_runtime.h>
#include <cstdint>

#define B_DIM  64
#define S_DIM  2048
#define D_DIM  6
#define H_DIM  8
#define NC     32
#define CHUNK  32            // L: timesteps per chunk
#define NCHUNK 64            // C = S_DIM / CHUNK
#define EPS    1e-8f

// ---- scratch (device globals; no allocation allowed) ----
__device__ float g_delta[(size_t)B_DIM * S_DIM * H_DIM * NC];  // 134 MB
__device__ float g_psi  [(size_t)B_DIM * S_DIM * H_DIM * NC];  // 134 MB
__device__ float g_chunk[(size_t)B_DIM * H_DIM * NCHUNK * NC]; // 4.2 MB
__device__ float g_carry[(size_t)B_DIM * H_DIM * NCHUNK * NC]; // 4.2 MB

// ---- Cl(4,1) sign machinery ----
// sign(a,b) for blade product e_a e_b: reorder swaps + metric (e5*e5 = -1).
__host__ __device__ constexpr int cpopc(int v) {
    int c = 0;
    for (int i = 0; i < 5; ++i) c += (v >> i) & 1;
    return c;
}
__host__ __device__ constexpr bool sign_neg(int a, int b) {
    int s = 0;
    for (int t = 1; t < 5; ++t) s += cpopc((a >> t) & b);
    if (a & b & 16) s += 1;           // metric: bit 4 (e5) has -1 signature
    return (s & 1) != 0;
}

// GP(a, b)_k = sum_i sign(i, i^k) * a[i] * b[i^k]; signs are compile-time
// constants after full unroll -> free FFMA negate modifiers.
__device__ __forceinline__ void gp(const float* __restrict__ a,
                                   const float* __restrict__ b,
                                   float* __restrict__ o) {
#pragma unroll
    for (int k = 0; k < NC; ++k) {
        float acc = 0.f;
#pragma unroll
        for (int i = 0; i < NC; ++i) {
            if (sign_neg(i, i ^ k)) acc = fmaf(-a[i], b[i ^ k], acc);
            else                    acc = fmaf( a[i], b[i ^ k], acc);
        }
        o[k] = acc;
    }
}

__device__ __forceinline__ void norm32(float* v) {
    float ss = 0.f;
#pragma unroll
    for (int k = 0; k < NC; ++k) ss = fmaf(v[k], v[k], ss);
    float inv = 1.f / (sqrtf(ss) + EPS);
#pragma unroll
    for (int k = 0; k < NC; ++k) v[k] *= inv;
}

__device__ __forceinline__ void load32(const float* __restrict__ p, float* v) {
#pragma unroll
    for (int q = 0; q < 8; ++q) {
        float4 t = reinterpret_cast<const float4*>(p)[q];
        v[4 * q + 0] = t.x; v[4 * q + 1] = t.y;
        v[4 * q + 2] = t.z; v[4 * q + 3] = t.w;
    }
}
__device__ __forceinline__ void store32(float* __restrict__ p, const float* v) {
#pragma unroll
    for (int q = 0; q < 8; ++q) {
        float4 t;
        t.x = v[4 * q + 0]; t.y = v[4 * q + 1];
        t.z = v[4 * q + 2]; t.w = v[4 * q + 3];
        reinterpret_cast<float4*>(p)[q] = t;
    }
}

// ---- Kernel A: delta_t = N(x_t @ W_in + b_in + e0), all (b,t,h) ----
// block = 256 threads = 8 warps = 8 heads of one (b,t); lane = component k.
__global__ void kA_delta(const float* __restrict__ x,
                         const float* __restrict__ Win,
                         const float* __restrict__ bin) {
    int bt = blockIdx.x;                 // 0 .. B*S-1
    int h  = threadIdx.x >> 5;
    int k  = threadIdx.x & 31;
    const float* xr = x + (size_t)bt * D_DIM;
    int col = h * NC + k;
    float u = bin[col];
#pragma unroll
    for (int d = 0; d < D_DIM; ++d)
        u = fmaf(xr[d], Win[d * (H_DIM * NC) + col], u);
    if (k == 0) u += 1.f;
    float ss = u * u;
#pragma unroll
    for (int o = 16; o > 0; o >>= 1) ss += __shfl_xor_sync(0xffffffffu, ss, o);
    float inv = 1.f / (sqrtf(ss) + EPS);
    g_delta[((size_t)bt * H_DIM + h) * NC + k] = u * inv;
}

// ---- Kernel B: per-chunk products, thread per (b,h,c) ----
__global__ void kB_chunk() {
    int tid = blockIdx.x * blockDim.x + threadIdx.x;   // 0 .. 32767
    int c = tid & (NCHUNK - 1);
    int h = (tid >> 6) & (H_DIM - 1);
    int b = tid >> 9;
    size_t t0 = (size_t)c * CHUNK;
    const float* base = g_delta + (((size_t)b * S_DIM + t0) * H_DIM + h) * NC;

    float P[NC];
    load32(base, P);
#pragma unroll 1
    for (int j = 1; j < CHUNK; ++j) {
        float Dv[NC], O[NC];
        load32(base + (size_t)j * H_DIM * NC, Dv);
        gp(Dv, P, O);        // new element multiplies on the LEFT
        norm32(O);
#pragma unroll
        for (int k = 0; k < NC; ++k) P[k] = O[k];
    }
    store32(g_chunk + (((size_t)(b * H_DIM + h)) * NCHUNK + c) * NC, P);
}

// ---- Kernel C: exclusive scan over chunk products, warp per (b,h) ----
// Uses shuffle GP with GF(2)-bilinear sign decomposition:
// sign(i, i^k) = (-1)^{g(i)} * (-1)^{parity(popc(i & m_k))}
__global__ void kC_scan() {
    int b = blockIdx.x;
    int h = threadIdx.x >> 5;
    int k = threadIdx.x & 31;

    int m = 0;
#pragma unroll
    for (int p = 0; p < 5; ++p) {
        int bit = __popc(k & ((1 << p) - 1)) & 1;
        m |= bit << p;
    }
    m ^= (k & 16);
    unsigned smask = 0u;
#pragma unroll
    for (int i = 0; i < NC; ++i)
        smask |= (unsigned)(__popc(i & m) & 1) << i;
    int pc = __popc(k);
    bool gneg = (((pc * (pc - 1) / 2) + ((k >> 4) & 1)) & 1) != 0;

    float r = (k == 0) ? 1.f : 0.f;     // psi0 = identity rotor
    size_t base = ((size_t)(b * H_DIM + h)) * NCHUNK * NC;
#pragma unroll 1
    for (int c = 0; c < NCHUNK; ++c) {
        g_carry[base + (size_t)c * NC + k] = r;     // exclusive prefix
        float a = g_chunk[base + (size_t)c * NC + k];
        if (gneg) a = -a;                           // fold (-1)^{g(i)} at source lane
        float acc = 0.f;
#pragma unroll
        for (int i = 0; i < NC; ++i) {
            float va = __shfl_sync(0xffffffffu, a, i);      // a_i
            float vr = __shfl_xor_sync(0xffffffffu, r, i);  // r_{i^k}
            unsigned sb = (smask << (31 - i)) & 0x80000000u;
            va = __uint_as_float(__float_as_uint(va) ^ sb);
            acc = fmaf(va, vr, acc);
        }
        float ss = acc * acc;
#pragma unroll
        for (int o = 16; o > 0; o >>= 1) ss += __shfl_xor_sync(0xffffffffu, ss, o);
        r = acc * (1.f / (sqrtf(ss) + EPS));
    }
}

// ---- Kernel D: expand within chunk using carry, write psi_seq ----
__global__ void kD_expand() {
    int tid = blockIdx.x * blockDim.x + threadIdx.x;   // 0 .. 32767
    int c = tid & (NCHUNK - 1);
    int h = (tid >> 6) & (H_DIM - 1);
    int b = tid >> 9;
    size_t t0 = (size_t)c * CHUNK;
    const float* dbase = g_delta + (((size_t)b * S_DIM + t0) * H_DIM + h) * NC;
    float*       pbase = g_psi   + (((size_t)b * S_DIM + t0) * H_DIM + h) * NC;

    float P[NC];
    load32(g_carry + (((size_t)(b * H_DIM + h)) * NCHUNK + c) * NC, P);
#pragma unroll 1
    for (int j = 0; j < CHUNK; ++j) {
        float Dv[NC], O[NC];
        load32(dbase + (size_t)j * H_DIM * NC, Dv);
        gp(Dv, P, O);
        norm32(O);
#pragma unroll
        for (int k = 0; k < NC; ++k) P[k] = O[k];
        store32(pbase + (size_t)j * H_DIM * NC, P);
    }
}

// ---- Kernel E: out = N(psi_row @ W_out + b_out), thread per (b,t) row ----
__global__ void kE_proj(const float* __restrict__ Wout,
                        const float* __restrict__ bout,
                        float* __restrict__ out) {
    __shared__ float sW[H_DIM * NC * NC];   // 256x32 = 32 KB
    __shared__ float sb[NC];
    for (int i = threadIdx.x; i < H_DIM * NC * NC; i += blockDim.x)
        sW[i] = Wout[i];
    if (threadIdx.x < NC) sb[threadIdx.x] = bout[threadIdx.x];
    __syncthreads();

    size_t r = (size_t)blockIdx.x * blockDim.x + threadIdx.x;  // row id
    const float4* prow = reinterpret_cast<const float4*>(g_psi + r * (H_DIM * NC));

    float acc[NC];
#pragma unroll
    for (int k = 0; k < NC; ++k) acc[k] = sb[k];

#pragma unroll 1
    for (int m4 = 0; m4 < (H_DIM * NC) / 4; ++m4) {
        float4 pv = prow[m4];
        float pvv[4] = {pv.x, pv.y, pv.z, pv.w};
#pragma unroll
        for (int mm = 0; mm < 4; ++mm) {
            float pm = pvv[mm];
            const float4* wrow =
                reinterpret_cast<const float4*>(sW + (m4 * 4 + mm) * NC);
#pragma unroll
            for (int kk = 0; kk < 8; ++kk) {
                float4 w = wrow[kk];   // warp-uniform address -> LDS broadcast
                acc[4 * kk + 0] = fmaf(pm, w.x, acc[4 * kk + 0]);
                acc[4 * kk + 1] = fmaf(pm, w.y, acc[4 * kk + 1]);
                acc[4 * kk + 2] = fmaf(pm, w.z, acc[4 * kk + 2]);
                acc[4 * kk + 3] = fmaf(pm, w.w, acc[4 * kk + 3]);
            }
        }
    }

    float ss = 0.f;
#pragma unroll
    for (int k = 0; k < NC; ++k) ss = fmaf(acc[k], acc[k], ss);
    float inv = 1.f / (sqrtf(ss) + EPS);
    float4* orow = reinterpret_cast<float4*>(out + r * NC);
#pragma unroll
    for (int q = 0; q < 8; ++q) {
        float4 v;
        v.x = acc[4 * q + 0] * inv; v.y = acc[4 * q + 1] * inv;
        v.z = acc[4 * q + 2] * inv; v.w = acc[4 * q + 3] * inv;
        orow[q] = v;
    }
}

extern "C" void kernel_launch(void* const* d_in, const int* in_sizes, int n_in,
                              void* d_out, int out_size) {
    const float* x    = (const float*)d_in[0];
    const float* Win  = (const float*)d_in[1];
    const float* bin  = (const float*)d_in[2];
    const float* Wout = (const float*)d_in[3];
    const float* bout = (const float*)d_in[4];
    float* out = (float*)d_out;

    kA_delta<<<B_DIM * S_DIM, 256>>>(x, Win, bin);
    kB_chunk<<<(B_DIM * H_DIM * NCHUNK) / 128, 128>>>();
    kC_scan<<<B_DIM, H_DIM * 32>>>();
    kD_expand<<<(B_DIM * H_DIM * NCHUNK) / 128, 128>>>();
    kE_proj<<<(B_DIM * S_DIM) / 256, 256>>>(Wout, bout, out);
}

// round 4
// speedup vs baseline: 1.4507x; 1.4507x over previous
#include <cuda_runtime.h>
#include <cstdint>

#define B_DIM  64
#define S_DIM  2048
#define D_DIM  6
#define H_DIM  8
#define NC     32
#define CHUNK  8             // timesteps per chunk
#define NCHUNK 256           // chunks per chain
#define GRP    16            // chunks per scan group
#define NGRP   16            // groups per chain
#define EPS    1e-8f

// ---- scratch (device globals; no allocation allowed) ----
__device__ float g_psi  [(size_t)B_DIM * S_DIM * H_DIM * NC];   // intra-chunk prefixes (134 MB)
__device__ float g_chunk[(size_t)B_DIM * H_DIM * NCHUNK * NC];  // chunk products (16.8 MB)
__device__ float g_scan [(size_t)B_DIM * H_DIM * NCHUNK * NC];  // within-group inclusive scans
__device__ float g_gcar [(size_t)B_DIM * H_DIM * NGRP * NC];    // group exclusive carries
__device__ float g_carry[(size_t)B_DIM * H_DIM * NCHUNK * NC];  // per-chunk exclusive carries

// ---- Cl(4,1) sign machinery (validated R1) ----
__host__ __device__ constexpr int cpopc(int v) {
    int c = 0;
    for (int i = 0; i < 5; ++i) c += (v >> i) & 1;
    return c;
}
__host__ __device__ constexpr bool sign_neg(int a, int b) {
    int s = 0;
    for (int t = 1; t < 5; ++t) s += cpopc((a >> t) & b);
    if (a & b & 16) s += 1;           // metric: e5*e5 = -1
    return (s & 1) != 0;
}

__device__ __forceinline__ void gp(const float* __restrict__ a,
                                   const float* __restrict__ b,
                                   float* __restrict__ o) {
#pragma unroll
    for (int k = 0; k < NC; ++k) {
        float acc = 0.f;
#pragma unroll
        for (int i = 0; i < NC; ++i) {
            if (sign_neg(i, i ^ k)) acc = fmaf(-a[i], b[i ^ k], acc);
            else                    acc = fmaf( a[i], b[i ^ k], acc);
        }
        o[k] = acc;
    }
}

__device__ __forceinline__ void norm32(float* v) {
    float ss = 0.f;
#pragma unroll
    for (int k = 0; k < NC; ++k) ss = fmaf(v[k], v[k], ss);
    float inv = 1.f / (sqrtf(ss) + EPS);
#pragma unroll
    for (int k = 0; k < NC; ++k) v[k] *= inv;
}

__device__ __forceinline__ void load32(const float* __restrict__ p, float* v) {
#pragma unroll
    for (int q = 0; q < 8; ++q) {
        float4 t = reinterpret_cast<const float4*>(p)[q];
        v[4 * q + 0] = t.x; v[4 * q + 1] = t.y;
        v[4 * q + 2] = t.z; v[4 * q + 3] = t.w;
    }
}
__device__ __forceinline__ void store32(float* __restrict__ p, const float* v) {
#pragma unroll
    for (int q = 0; q < 8; ++q) {
        float4 t;
        t.x = v[4 * q + 0]; t.y = v[4 * q + 1];
        t.z = v[4 * q + 2]; t.w = v[4 * q + 3];
        reinterpret_cast<float4*>(p)[q] = t;
    }
}

// ---- f32x2 packed helpers ----
__device__ __forceinline__ unsigned long long pack2(float lo, float hi) {
    unsigned long long r;
    asm("mov.b64 %0, {%1, %2};" : "=l"(r) : "f"(lo), "f"(hi));
    return r;
}
__device__ __forceinline__ void unpack2(unsigned long long v, float& lo, float& hi) {
    asm("mov.b64 {%0, %1}, %2;" : "=f"(lo), "=f"(hi) : "l"(v));
}
__device__ __forceinline__ unsigned long long ffma2(unsigned long long a,
                                                    unsigned long long b,
                                                    unsigned long long c) {
    unsigned long long d;
    asm("fma.rn.f32x2 %0, %1, %2, %3;" : "=l"(d) : "l"(a), "l"(b), "l"(c));
    return d;
}

// ---- per-lane sign setup for shuffle GP (validated R1) ----
__device__ __forceinline__ void lane_sign(int k, unsigned& smask, bool& gneg) {
    int m = 0;
#pragma unroll
    for (int p = 0; p < 5; ++p) {
        int bit = __popc(k & ((1 << p) - 1)) & 1;
        m |= bit << p;
    }
    m ^= (k & 16);
    smask = 0u;
#pragma unroll
    for (int i = 0; i < NC; ++i)
        smask |= (unsigned)(__popc(i & m) & 1) << i;
    int pc = __popc(k);
    gneg = (((pc * (pc - 1) / 2) + ((k >> 4) & 1)) & 1) != 0;
}

// one shuffle-GP step: r <- N(GP(a, r)); a pre-negated by gneg at caller
__device__ __forceinline__ float shfl_gp_norm(float a, float r, unsigned smask) {
    float acc = 0.f;
#pragma unroll
    for (int i = 0; i < NC; ++i) {
        float va = __shfl_sync(0xffffffffu, a, i);
        float vr = __shfl_xor_sync(0xffffffffu, r, i);
        unsigned sb = (smask << (31 - i)) & 0x80000000u;
        va = __uint_as_float(__float_as_uint(va) ^ sb);
        acc = fmaf(va, vr, acc);
    }
    float ss = acc * acc;
#pragma unroll
    for (int o = 16; o > 0; o >>= 1) ss += __shfl_xor_sync(0xffffffffu, ss, o);
    return acc * (1.f / (sqrtf(ss) + EPS));
}

// ---- Kernel AB: fused delta computation + chunk products + intra-chunk prefixes ----
// thread per (b,h,c); writes prefixes to g_psi, chunk totals to g_chunk
__global__ void kAB(const float* __restrict__ x,
                    const float* __restrict__ Win,
                    const float* __restrict__ bin) {
    __shared__ float sW[D_DIM * H_DIM * NC];   // 6 KB
    __shared__ float sB[H_DIM * NC];
    for (int i = threadIdx.x; i < D_DIM * H_DIM * NC; i += blockDim.x) sW[i] = Win[i];
    for (int i = threadIdx.x; i < H_DIM * NC; i += blockDim.x) sB[i] = bin[i];
    __syncthreads();

    int tid = blockIdx.x * blockDim.x + threadIdx.x;   // 0 .. 131071
    int c = tid & (NCHUNK - 1);
    int h = (tid >> 8) & (H_DIM - 1);
    int b = tid >> 11;
    size_t t0 = (size_t)c * CHUNK;
    const float* bcol = sB + h * NC;

    float P[NC];
#pragma unroll 1
    for (int j = 0; j < CHUNK; ++j) {
        size_t t = t0 + j;
        const float* xr = x + ((size_t)b * S_DIM + t) * D_DIM;
        float2 x01 = reinterpret_cast<const float2*>(xr)[0];
        float2 x23 = reinterpret_cast<const float2*>(xr)[1];
        float2 x45 = reinterpret_cast<const float2*>(xr)[2];
        float xv[D_DIM] = {x01.x, x01.y, x23.x, x23.y, x45.x, x45.y};

        float u[NC];
#pragma unroll
        for (int k = 0; k < NC; ++k) {
            float a = bcol[k];
#pragma unroll
            for (int d = 0; d < D_DIM; ++d)
                a = fmaf(xv[d], sW[d * (H_DIM * NC) + h * NC + k], a);
            u[k] = a;
        }
        u[0] += 1.f;
        norm32(u);                       // u is now delta_t

        if (j == 0) {
#pragma unroll
            for (int k = 0; k < NC; ++k) P[k] = u[k];
        } else {
            float O[NC];
            gp(u, P, O);                 // newer delta on the LEFT
            norm32(O);
#pragma unroll
            for (int k = 0; k < NC; ++k) P[k] = O[k];
        }
        store32(g_psi + ((size_t)(b * S_DIM + t) * H_DIM + h) * NC, P);
    }
    store32(g_chunk + (((size_t)(b * H_DIM + h)) * NCHUNK + c) * NC, P);
}

// ---- kC1: within-group inclusive scan of chunk products, warp per (b,h,g) ----
__global__ void kC1() {
    int w = blockIdx.x * (blockDim.x >> 5) + (threadIdx.x >> 5);  // 0..8191
    int k = threadIdx.x & 31;
    int g = w & (NGRP - 1);
    int h = (w >> 4) & (H_DIM - 1);
    int b = w >> 7;
    unsigned smask; bool gneg;
    lane_sign(k, smask, gneg);

    size_t base = (((size_t)(b * H_DIM + h)) * NCHUNK + (size_t)g * GRP) * NC;
    float r = g_chunk[base + k];         // inclusive: first element is itself
    g_scan[base + k] = r;
#pragma unroll 1
    for (int j = 1; j < GRP; ++j) {
        float a = g_chunk[base + (size_t)j * NC + k];
        if (gneg) a = -a;
        r = shfl_gp_norm(a, r, smask);
        g_scan[base + (size_t)j * NC + k] = r;
    }
}

// ---- kC2: exclusive scan of NGRP group totals, warp per (b,h) ----
__global__ void kC2() {
    int w = blockIdx.x * (blockDim.x >> 5) + (threadIdx.x >> 5);  // 0..511
    int k = threadIdx.x & 31;
    int h = w & (H_DIM - 1);
    int b = w >> 3;
    unsigned smask; bool gneg;
    lane_sign(k, smask, gneg);

    size_t cb = ((size_t)(b * H_DIM + h)) * NGRP * NC;
    size_t sb = ((size_t)(b * H_DIM + h)) * NCHUNK * NC;
    float r = (k == 0) ? 1.f : 0.f;      // identity rotor
#pragma unroll 1
    for (int g = 0; g < NGRP; ++g) {
        g_gcar[cb + (size_t)g * NC + k] = r;               // exclusive
        float a = g_scan[sb + ((size_t)g * GRP + GRP - 1) * NC + k];  // group total
        if (gneg) a = -a;
        r = shfl_gp_norm(a, r, smask);
    }
}

// ---- kC3: final per-chunk exclusive carries, thread per (b,h,c) ----
__global__ void kC3() {
    int tid = blockIdx.x * blockDim.x + threadIdx.x;   // 0 .. 131071
    int c = tid & (NCHUNK - 1);
    int h = (tid >> 8) & (H_DIM - 1);
    int b = tid >> 11;
    int g = c >> 4;

    size_t cb = (((size_t)(b * H_DIM + h)) * NCHUNK + c) * NC;
    float G[NC];
    load32(g_gcar + ((size_t)(b * H_DIM + h)) * NGRP * NC + (size_t)g * NC, G);
    if ((c & (GRP - 1)) == 0) {
        store32(g_carry + cb, G);
    } else {
        float A[NC], O[NC];
        load32(g_scan + cb - NC, A);     // within-group inclusive up to c-1 (newer)
        gp(A, G, O);
        norm32(O);
        store32(g_carry + cb, O);
    }
}

// ---- kDE: fused expand + projection. thread per (b,t) row ----
// psi[b,t,h] = N(GP(pref[b,t,h], carry[b,h,t/8])); out = N(psi_row @ Wout + bout)
__global__ void kDE(const float* __restrict__ Wout,
                    const float* __restrict__ bout,
                    float* __restrict__ out) {
    __shared__ float sW[H_DIM * NC * NC];   // 32 KB
    __shared__ float sb[NC];
    for (int i = threadIdx.x; i < H_DIM * NC * NC; i += blockDim.x) sW[i] = Wout[i];
    if (threadIdx.x < NC) sb[threadIdx.x] = bout[threadIdx.x];
    __syncthreads();

    int tid = blockIdx.x * blockDim.x + threadIdx.x;   // row = b*S + t
    size_t row = (size_t)tid;
    int t = tid & (S_DIM - 1);
    int b = tid >> 11;
    int c = t >> 3;

    unsigned long long acc2[16];
#pragma unroll
    for (int j = 0; j < 16; ++j) acc2[j] = pack2(sb[2 * j], sb[2 * j + 1]);

#pragma unroll 1
    for (int h = 0; h < H_DIM; ++h) {
        float A[NC], Cv[NC], O[NC];
        load32(g_psi + (row * H_DIM + h) * NC, A);
        load32(g_carry + (((size_t)(b * H_DIM + h)) * NCHUNK + c) * NC, Cv);
        gp(A, Cv, O);                    // prefix (newer) on LEFT
        float ss = 0.f;
#pragma unroll
        for (int k = 0; k < NC; ++k) ss = fmaf(O[k], O[k], ss);
        float inv = 1.f / (sqrtf(ss) + EPS);

#pragma unroll
        for (int m = 0; m < NC; ++m) {
            float pm = O[m] * inv;
            unsigned long long pm2 = pack2(pm, pm);
            const ulonglong2* wr =
                reinterpret_cast<const ulonglong2*>(sW + (size_t)(h * NC + m) * NC);
#pragma unroll
            for (int q = 0; q < 8; ++q) {
                ulonglong2 wv = wr[q];   // warp-uniform smem address -> broadcast
                acc2[2 * q + 0] = ffma2(pm2, wv.x, acc2[2 * q + 0]);
                acc2[2 * q + 1] = ffma2(pm2, wv.y, acc2[2 * q + 1]);
            }
        }
    }

    float res[NC];
    float ss = 0.f;
#pragma unroll
    for (int j = 0; j < 16; ++j) {
        float lo, hi;
        unpack2(acc2[j], lo, hi);
        res[2 * j] = lo; res[2 * j + 1] = hi;
        ss = fmaf(lo, lo, fmaf(hi, hi, ss));
    }
    float inv = 1.f / (sqrtf(ss) + EPS);
    float4* orow = reinterpret_cast<float4*>(out + row * NC);
#pragma unroll
    for (int q = 0; q < 8; ++q) {
        float4 v;
        v.x = res[4 * q + 0] * inv; v.y = res[4 * q + 1] * inv;
        v.z = res[4 * q + 2] * inv; v.w = res[4 * q + 3] * inv;
        orow[q] = v;
    }
}

extern "C" void kernel_launch(void* const* d_in, const int* in_sizes, int n_in,
                              void* d_out, int out_size) {
    const float* x    = (const float*)d_in[0];
    const float* Win  = (const float*)d_in[1];
    const float* bin  = (const float*)d_in[2];
    const float* Wout = (const float*)d_in[3];
    const float* bout = (const float*)d_in[4];
    float* out = (float*)d_out;

    kAB<<<(B_DIM * H_DIM * NCHUNK) / 128, 128>>>(x, Win, bin);
    kC1<<<(B_DIM * H_DIM * NGRP) / 8, 256>>>();
    kC2<<<(B_DIM * H_DIM) / 8, 256>>>();
    kC3<<<(B_DIM * H_DIM * NCHUNK) / 128, 128>>>();
    kDE<<<(B_DIM * S_DIM) / 128, 128>>>(Wout, bout, out);
}